// round 15
// baseline (speedup 1.0000x reference)
#include <cuda_runtime.h>
#include <cstdint>

// MultiLevelEmbedding: out[b,t,:] = emb_tables[level_ids[b,t], token_ids[b,t], :]
//                                   + level_embed[level_ids[b,t], :]
// B=64, T=1024, L=4, VOCAB=258, D=512 (float32).
//
// R15 = R14 (chunk-split warps: warp owns a fixed 128B column chunk; 4
// level_embed float4 in registers; lane-parallel index fetch + shfl
// broadcast) tuned for occupancy and amortization:
//  - __launch_bounds__(256, 6): cap regs ~40 -> 6 blocks/SM (occ 75% ceil,
//    was 52.8% at 48 regs) to cover the load->FADD->store chain.
//  - ROWS_PW 16: lanes 0-15 fetch indices (same 2 LDG wavefronts, 2x rows),
//    halves per-row prologue cost; grid 2048 blocks.
//  - Incremented store pointer (output rows consecutive) cuts IMAD issue.
// Data path per row-chunk: 1 LDG.128 + FSEL-add + 1 STG.128 (pure-gather
// wavefront count; the ~24.5 us output-write wall from R3/R5/R7).
// Index dtype (int64 vs int32) via per-warp ballot on odd 32-bit words of
// token_ids (values < 258 => odd words all-zero iff int64; P(false) ~ 0).

#define D_VEC     128                 // float4 per row (D=512)
#define VOCAB_SZ  258
#define N_POS     (64 * 1024)         // B*T rows
#define ROWS_PW   16                  // rows per warp (per chunk)
#define FULL      0xffffffffu

#define SEL_ADD(dst, A, L)                                             \
    do {                                                               \
        float4 _b;                                                     \
        _b.x = (L)==0 ? b0.x : (L)==1 ? b1.x : (L)==2 ? b2.x : b3.x;   \
        _b.y = (L)==0 ? b0.y : (L)==1 ? b1.y : (L)==2 ? b2.y : b3.y;   \
        _b.z = (L)==0 ? b0.z : (L)==1 ? b1.z : (L)==2 ? b2.z : b3.z;   \
        _b.w = (L)==0 ? b0.w : (L)==1 ? b1.w : (L)==2 ? b2.w : b3.w;   \
        (dst).x = (A).x + _b.x; (dst).y = (A).y + _b.y;                \
        (dst).z = (A).z + _b.z; (dst).w = (A).w + _b.w;                \
    } while (0)

__global__ __launch_bounds__(256, 6)
void mle_kernel(const void* __restrict__ level_ids_raw,
                const void* __restrict__ token_ids_raw,
                const float4* __restrict__ emb_tables,
                const float4* __restrict__ level_embed,
                float4* __restrict__ out) {
    const int lane  = threadIdx.x & 31;
    const int warp  = (blockIdx.x * 256 + threadIdx.x) >> 5;  // 0..16383
    const int chunk = warp & 3;                // which 32-float4 chunk
    const int rbase = (warp >> 2) * ROWS_PW;   // first row of this group
    const int cofs  = chunk * 32 + lane;       // column (float4 units)

    // ---- dtype detection (1 LDG + ballot, warp-uniform) ----
    const uint32_t* tr = (const uint32_t*)token_ids_raw;
    const unsigned nz  = __ballot_sync(FULL, tr[2 * lane + 1] != 0u);
    const bool is64    = (nz == 0u);

    // ---- this chunk's level_embed values for all 4 levels (16 regs) ----
    const float4 b0 = __ldg(level_embed + 0 * D_VEC + cofs);
    const float4 b1 = __ldg(level_embed + 1 * D_VEC + cofs);
    const float4 b2 = __ldg(level_embed + 2 * D_VEC + cofs);
    const float4 b3 = __ldg(level_embed + 3 * D_VEC + cofs);

    // ---- lane-parallel index fetch: lanes 0-15 own one row each ----
    int lv = 0, ro = 0;                // level, table row offset
    if (lane < ROWS_PW) {
        const int p = rbase + lane;
        int tv;
        if (is64) {
            lv = (int)((const long long*)level_ids_raw)[p];
            tv = (int)((const long long*)token_ids_raw)[p];
        } else {
            lv = ((const int*)level_ids_raw)[p];
            tv = ((const int*)token_ids_raw)[p];
        }
        ro = lv * VOCAB_SZ + tv;
    }

    // incremented output pointer: rows are consecutive
    float4* optr = out + (long long)rbase * D_VEC + cofs;

    #pragma unroll
    for (int r = 0; r < ROWS_PW; r += 4) {
        // broadcast row offsets + levels from owning lanes (SHFL pipe)
        const int ro0 = __shfl_sync(FULL, ro, r);
        const int ro1 = __shfl_sync(FULL, ro, r + 1);
        const int ro2 = __shfl_sync(FULL, ro, r + 2);
        const int ro3 = __shfl_sync(FULL, ro, r + 3);
        const int l0  = __shfl_sync(FULL, lv, r);
        const int l1  = __shfl_sync(FULL, lv, r + 1);
        const int l2  = __shfl_sync(FULL, lv, r + 2);
        const int l3  = __shfl_sync(FULL, lv, r + 3);

        // 4 independent table loads in flight (128B coalesced each)
        const float4 a0 = __ldg(emb_tables + ro0 * D_VEC + cofs);
        const float4 a1 = __ldg(emb_tables + ro1 * D_VEC + cofs);
        const float4 a2 = __ldg(emb_tables + ro2 * D_VEC + cofs);
        const float4 a3 = __ldg(emb_tables + ro3 * D_VEC + cofs);

        float4 r0, r1, r2, r3;
        SEL_ADD(r0, a0, l0);
        SEL_ADD(r1, a1, l1);
        SEL_ADD(r2, a2, l2);
        SEL_ADD(r3, a3, l3);

        __stcs(optr,             r0);
        __stcs(optr + D_VEC,     r1);
        __stcs(optr + 2 * D_VEC, r2);
        __stcs(optr + 3 * D_VEC, r3);
        optr += 4 * D_VEC;
    }
}

extern "C" void kernel_launch(void* const* d_in, const int* in_sizes, int n_in,
                              void* d_out, int out_size) {
    const void*   level_ids  = d_in[0];
    const void*   token_ids  = d_in[1];
    const float4* emb_tables = (const float4*)d_in[2];
    const float4* level_emb  = (const float4*)d_in[3];
    float4*       out        = (float4*)d_out;

    // 16384 warps (4 chunk-warps x 4096 row-groups) / 8 warps per block
    mle_kernel<<<2048, 256>>>(level_ids, token_ids,
                              emb_tables, level_emb, out);
}

// round 16
// speedup vs baseline: 1.4366x; 1.4366x over previous
#include <cuda_runtime.h>
#include <cstdint>

// MultiLevelEmbedding: out[b,t,:] = emb_tables[level_ids[b,t], token_ids[b,t], :]
//                                   + level_embed[level_ids[b,t], :]
// B=64, T=1024, L=4, VOCAB=258, D=512 (float32).
//
// R16 = R14 (chunk-split warps, lane-parallel index fetch) with three
// issue/MLP trims (R15 lesson: never cap regs below the in-flight loads):
//  1. All 8 rows' table loads issued up front (ulonglong2) -> MLP 8,
//     matching the pure gather's load structure (~24.5 us write wall).
//  2. (level, rowoff) packed into one int -> 1 SHFL per row (was 2).
//  3. add.rn.f32x2 packed adds + 64-bit integer selects: per row
//     12 SEL (alu) + 2 ADD (fma) vs 12 FSEL + 4 FADD.
// Index dtype (int64 vs int32) via per-warp ballot on odd 32-bit words of
// token_ids (values < 258 => odd words all-zero iff int64; P(false) ~ 0).

#define D_VEC     128                 // 16B units per row (D=512 floats)
#define VOCAB_SZ  258
#define N_POS     (64 * 1024)
#define ROWS_PW   8
#define FULL      0xffffffffu

typedef unsigned long long ull;

__device__ __forceinline__ ull addf32x2(ull a, ull b) {
    ull r;
    asm("add.rn.f32x2 %0, %1, %2;" : "=l"(r) : "l"(a), "l"(b));
    return r;
}
__device__ __forceinline__ ull packf2(float x, float y) {
    ull r;
    asm("mov.b64 %0, {%1, %2};" : "=l"(r) : "f"(x), "f"(y));
    return r;
}

// 64-bit 4-way select on warp-uniform level, then packed add + store.
#define ROW_OP(A, K, OP)                                                  \
    do {                                                                  \
        const int _l = (K) >> 12;                                         \
        const ull _slo = _l==0 ? b0lo : _l==1 ? b1lo : _l==2 ? b2lo : b3lo;\
        const ull _shi = _l==0 ? b0hi : _l==1 ? b1hi : _l==2 ? b2hi : b3hi;\
        ulonglong2 _r;                                                    \
        _r.x = addf32x2((A).x, _slo);                                     \
        _r.y = addf32x2((A).y, _shi);                                     \
        __stcs((OP), _r);                                                 \
    } while (0)

__global__ __launch_bounds__(256)
void mle_kernel(const void* __restrict__ level_ids_raw,
                const void* __restrict__ token_ids_raw,
                const ulonglong2* __restrict__ emb_tables,
                const float4* __restrict__ level_embed,
                ulonglong2* __restrict__ out) {
    const int lane  = threadIdx.x & 31;
    const int warp  = (blockIdx.x * 256 + threadIdx.x) >> 5;  // 0..32767
    const int chunk = warp & 3;
    const int rbase = (warp >> 2) * ROWS_PW;
    const int cofs  = chunk * 32 + lane;       // column in 16B units

    // ---- dtype detection (1 LDG + ballot, warp-uniform) ----
    const uint32_t* tr = (const uint32_t*)token_ids_raw;
    const unsigned nz  = __ballot_sync(FULL, tr[2 * lane + 1] != 0u);
    const bool is64    = (nz == 0u);

    // ---- this chunk's level_embed for all 4 levels, packed (16 regs) ----
    const float4 f0 = __ldg(level_embed + 0 * D_VEC + cofs);
    const float4 f1 = __ldg(level_embed + 1 * D_VEC + cofs);
    const float4 f2 = __ldg(level_embed + 2 * D_VEC + cofs);
    const float4 f3 = __ldg(level_embed + 3 * D_VEC + cofs);
    const ull b0lo = packf2(f0.x, f0.y), b0hi = packf2(f0.z, f0.w);
    const ull b1lo = packf2(f1.x, f1.y), b1hi = packf2(f1.z, f1.w);
    const ull b2lo = packf2(f2.x, f2.y), b2hi = packf2(f2.z, f2.w);
    const ull b3lo = packf2(f3.x, f3.y), b3hi = packf2(f3.z, f3.w);

    // ---- lane-parallel index fetch: lanes 0-7, key = (l<<12)|rowoff ----
    int key = 0;
    if (lane < ROWS_PW) {
        const int p = rbase + lane;
        int lv, tv;
        if (is64) {
            lv = (int)((const long long*)level_ids_raw)[p];
            tv = (int)((const long long*)token_ids_raw)[p];
        } else {
            lv = ((const int*)level_ids_raw)[p];
            tv = ((const int*)token_ids_raw)[p];
        }
        key = (lv << 12) | (lv * VOCAB_SZ + tv);
    }

    // ---- broadcast keys: 1 SHFL per row ----
    const int k0 = __shfl_sync(FULL, key, 0);
    const int k1 = __shfl_sync(FULL, key, 1);
    const int k2 = __shfl_sync(FULL, key, 2);
    const int k3 = __shfl_sync(FULL, key, 3);
    const int k4 = __shfl_sync(FULL, key, 4);
    const int k5 = __shfl_sync(FULL, key, 5);
    const int k6 = __shfl_sync(FULL, key, 6);
    const int k7 = __shfl_sync(FULL, key, 7);

    // ---- all 8 table loads in flight (MLP 8, 128B coalesced each) ----
    const ulonglong2 a0 = __ldg(emb_tables + (k0 & 0xFFF) * D_VEC + cofs);
    const ulonglong2 a1 = __ldg(emb_tables + (k1 & 0xFFF) * D_VEC + cofs);
    const ulonglong2 a2 = __ldg(emb_tables + (k2 & 0xFFF) * D_VEC + cofs);
    const ulonglong2 a3 = __ldg(emb_tables + (k3 & 0xFFF) * D_VEC + cofs);
    const ulonglong2 a4 = __ldg(emb_tables + (k4 & 0xFFF) * D_VEC + cofs);
    const ulonglong2 a5 = __ldg(emb_tables + (k5 & 0xFFF) * D_VEC + cofs);
    const ulonglong2 a6 = __ldg(emb_tables + (k6 & 0xFFF) * D_VEC + cofs);
    const ulonglong2 a7 = __ldg(emb_tables + (k7 & 0xFFF) * D_VEC + cofs);

    ulonglong2* optr = out + (long long)rbase * D_VEC + cofs;

    ROW_OP(a0, k0, optr);
    ROW_OP(a1, k1, optr + 1 * D_VEC);
    ROW_OP(a2, k2, optr + 2 * D_VEC);
    ROW_OP(a3, k3, optr + 3 * D_VEC);
    ROW_OP(a4, k4, optr + 4 * D_VEC);
    ROW_OP(a5, k5, optr + 5 * D_VEC);
    ROW_OP(a6, k6, optr + 6 * D_VEC);
    ROW_OP(a7, k7, optr + 7 * D_VEC);
}

extern "C" void kernel_launch(void* const* d_in, const int* in_sizes, int n_in,
                              void* d_out, int out_size) {
    const void*       level_ids  = d_in[0];
    const void*       token_ids  = d_in[1];
    const ulonglong2* emb_tables = (const ulonglong2*)d_in[2];
    const float4*     level_emb  = (const float4*)d_in[3];
    ulonglong2*       out        = (ulonglong2*)d_out;

    // 32768 warps (4 chunk-warps x 8192 row-groups) / 8 warps per block
    mle_kernel<<<4096, 256>>>(level_ids, token_ids,
                              emb_tables, level_emb, out);
}

// round 17
// speedup vs baseline: 1.4468x; 1.0071x over previous
#include <cuda_runtime.h>
#include <cstdint>

// MultiLevelEmbedding: out[b,t,:] = emb_tables[level_ids[b,t], token_ids[b,t], :]
//                                   + level_embed[level_ids[b,t], :]
// B=64, T=1024, L=4, VOCAB=258, D=512 (float32).
//
// R17 (final form): R9's two-kernel PDL structure — fuse prologue builds a
// 2.1 MB table, gather runs at the ~24.5-25.4 us output-write wall (the
// hardware floor established across R3/R5/R7: time is invariant to read-
// side optimization; 26.6 total is the fused-op plateau confirmed by three
// independent designs R9/R13/R14). Final trims:
//  - fuse grid 1032x128 (one block per table row, no tail, fast ramp)
//  - explicit cudaTriggerProgrammaticLaunchCompletion after fuse stores
//    releases the dependent gather at trigger time, not block retirement.
// Index dtype (int64 vs int32) via per-warp ballot on odd 32-bit words of
// token_ids (values < 258 => odd words all-zero iff int64; P(false) ~ 0).

#define D_VEC     128                 // float4 per row (D=512)
#define VOCAB_SZ  258
#define L_LVL     4
#define N_POS     (64 * 1024)         // B*T rows
#define N_ROWS    (L_LVL * VOCAB_SZ)  // 1032 table rows
#define FUSED_N   (N_ROWS * D_VEC)    // 132096 float4 = 2.1 MB

__device__ float4 g_fused[FUSED_N];

__global__ __launch_bounds__(128)
void fuse_kernel(const float4* __restrict__ emb_tables,
                 const float4* __restrict__ level_embed) {
    const int row = blockIdx.x;              // table row: l*VOCAB + v
    const int c   = threadIdx.x;             // column (float4 units)
    const int l   = row / VOCAB_SZ;
    const int i   = row * D_VEC + c;

    const float4 a = __ldg(emb_tables + i);
    const float4 b = __ldg(level_embed + l * D_VEC + c);
    float4 r;
    r.x = a.x + b.x; r.y = a.y + b.y; r.z = a.z + b.z; r.w = a.w + b.w;
    g_fused[i] = r;

    // Release the dependent gather grid as soon as this block's store is
    // issued (memory visibility is still enforced by the consumer's
    // cudaGridDependencySynchronize).
    cudaTriggerProgrammaticLaunchCompletion();
}

__global__ __launch_bounds__(256)
void gather_kernel(const void* __restrict__ level_ids_raw,
                   const void* __restrict__ token_ids_raw,
                   float4* __restrict__ out) {
    const int lane = threadIdx.x & 31;
    const int warp = (blockIdx.x * 256 + threadIdx.x) >> 5;
    const int pos0 = warp * 2;                // this warp's 2 rows
    const int pos1 = pos0 + 1;

    // ---- pre-sync work: dtype detection (1 LDG + ballot) ----
    const uint32_t* tr = (const uint32_t*)token_ids_raw;
    const unsigned nz  = __ballot_sync(0xffffffffu, tr[2 * lane + 1] != 0u);
    const bool is64    = (nz == 0u);

    // ---- pre-sync work: warp-uniform index loads (broadcast) ----
    long long l0, t0, l1, t1;
    if (is64) {
        l0 = ((const long long*)level_ids_raw)[pos0];
        t0 = ((const long long*)token_ids_raw)[pos0];
        l1 = ((const long long*)level_ids_raw)[pos1];
        t1 = ((const long long*)token_ids_raw)[pos1];
    } else {
        l0 = ((const int*)level_ids_raw)[pos0];
        t0 = ((const int*)token_ids_raw)[pos0];
        l1 = ((const int*)level_ids_raw)[pos1];
        t1 = ((const int*)token_ids_raw)[pos1];
    }

    const float4* __restrict__ r0 = g_fused + (l0 * VOCAB_SZ + t0) * D_VEC;
    const float4* __restrict__ r1 = g_fused + (l1 * VOCAB_SZ + t1) * D_VEC;
    float4* __restrict__ o0 = out + (long long)pos0 * D_VEC;
    float4* __restrict__ o1 = out + (long long)pos1 * D_VEC;

    // ---- wait for all fuse writes to be visible ----
    cudaGridDependencySynchronize();

    // ---- 8 independent loads first (MLP), then streaming stores ----
    float4 a0 = __ldg(r0 + lane);
    float4 a1 = __ldg(r0 + lane + 32);
    float4 a2 = __ldg(r0 + lane + 64);
    float4 a3 = __ldg(r0 + lane + 96);
    float4 b0 = __ldg(r1 + lane);
    float4 b1 = __ldg(r1 + lane + 32);
    float4 b2 = __ldg(r1 + lane + 64);
    float4 b3 = __ldg(r1 + lane + 96);

    __stcs(o0 + lane,      a0);
    __stcs(o0 + lane + 32, a1);
    __stcs(o0 + lane + 64, a2);
    __stcs(o0 + lane + 96, a3);
    __stcs(o1 + lane,      b0);
    __stcs(o1 + lane + 32, b1);
    __stcs(o1 + lane + 64, b2);
    __stcs(o1 + lane + 96, b3);
}

extern "C" void kernel_launch(void* const* d_in, const int* in_sizes, int n_in,
                              void* d_out, int out_size) {
    const void*   level_ids  = d_in[0];
    const void*   token_ids  = d_in[1];
    const float4* emb_tables = (const float4*)d_in[2];
    const float4* level_emb  = (const float4*)d_in[3];
    float4*       out        = (float4*)d_out;

    // Prologue: one block per table row.
    fuse_kernel<<<N_ROWS, 128>>>(emb_tables, level_emb);

    // Main gather under programmatic stream serialization.
    cudaLaunchConfig_t cfg = {};
    cfg.gridDim  = dim3(N_POS / 16);   // 2 rows/warp, 8 warps/block -> 4096
    cfg.blockDim = dim3(256);
    cfg.dynamicSmemBytes = 0;
    cfg.stream = 0;

    cudaLaunchAttribute attrs[1];
    attrs[0].id = cudaLaunchAttributeProgrammaticStreamSerialization;
    attrs[0].val.programmaticStreamSerializationAllowed = 1;
    cfg.attrs    = attrs;
    cfg.numAttrs = 1;

    cudaLaunchKernelEx(&cfg, gather_kernel,
                       (const void*)level_ids, (const void*)token_ids, out);
}